// round 11
// baseline (speedup 1.0000x reference)
#include <cuda_runtime.h>
#include <cuda_fp16.h>
#include <cuda_bf16.h>

#define N_NODES 100000
#define N_EDGES 3200000
#define E_TOT   (N_EDGES + N_NODES)
#define NEG_SLOPE 0.2f
#define N_TILES 98   // ceil(100000 / 1024)

// ---------------- device scratch (allocation-free contract) ----------------
__device__ int g_cnt[N_NODES];
__device__ int g_off[N_NODES + 1];
__device__ int g_cursor[N_NODES];
__device__ int g_csr_src[E_TOT];
__device__ int g_blk[N_TILES];

__device__ __align__(16) __half g_h1[N_NODES * 64];  // layer-1 features (half gather table)
__device__ __align__(16) float g_al1[N_NODES * 4];   // [als0, als1, ald0, ald1]
__device__ __align__(16) float g_hin2[N_NODES * 64]; // relu(layer-1 out), fp32 for matmul
__device__ __align__(16) __half g_h2[N_NODES * 64];  // layer-2 features (half gather table)
__device__ __align__(8)  float g_al2[N_NODES * 2];   // [als, ald]

// ---------------- CSR build ----------------
__global__ void k_init() {
    int i = blockIdx.x * blockDim.x + threadIdx.x;
    if (i < N_NODES) g_cnt[i] = 0;
}

// 4 edges per thread, int4 loads, independent no-return atomics (RED)
__global__ void k_hist(const int* __restrict__ ei) {
    int e0 = (blockIdx.x * blockDim.x + threadIdx.x) * 4;
    if (e0 + 4 <= N_EDGES) {
        int4 d = *reinterpret_cast<const int4*>(&ei[N_EDGES + e0]);
        atomicAdd(&g_cnt[d.x], 1);
        atomicAdd(&g_cnt[d.y], 1);
        atomicAdd(&g_cnt[d.z], 1);
        atomicAdd(&g_cnt[d.w], 1);
    } else {
        for (int e = e0; e < N_EDGES; ++e) atomicAdd(&g_cnt[ei[N_EDGES + e]], 1);
    }
}

// phase A: per-tile (1024) sums
__global__ void k_scan_a() {
    __shared__ int ws[32];
    int tid = threadIdx.x, lane = tid & 31, wid = tid >> 5;
    int i = blockIdx.x * 1024 + tid;
    int v = (i < N_NODES) ? g_cnt[i] : 0;
    #pragma unroll
    for (int d = 16; d; d >>= 1) v += __shfl_xor_sync(0xFFFFFFFFu, v, d);
    if (lane == 0) ws[wid] = v;
    __syncthreads();
    if (wid == 0) {
        int y = ws[lane];
        #pragma unroll
        for (int d = 16; d; d >>= 1) y += __shfl_xor_sync(0xFFFFFFFFu, y, d);
        if (lane == 0) g_blk[blockIdx.x] = y;
    }
}

// phase C: per-tile rescan + inline tile-offset + self-loop emission
// off[i] = exclusive_scan(cnt)[i] + i ; self-loop in slot off[i], edges after.
__global__ void k_scan_c() {
    __shared__ int warp_sums[32];
    __shared__ int s_blkoff;
    int tid = threadIdx.x, lane = tid & 31, wid = tid >> 5;
    if (wid == 0) {
        int ssum = 0;
        for (int j = lane; j < blockIdx.x; j += 32) ssum += g_blk[j];
        #pragma unroll
        for (int d = 16; d; d >>= 1) ssum += __shfl_xor_sync(0xFFFFFFFFu, ssum, d);
        if (lane == 0) s_blkoff = ssum;
    }
    int i = blockIdx.x * 1024 + tid;
    int v = (i < N_NODES) ? g_cnt[i] : 0;
    int x = v;
    #pragma unroll
    for (int d = 1; d < 32; d <<= 1) {
        int y = __shfl_up_sync(0xFFFFFFFFu, x, d);
        if (lane >= d) x += y;
    }
    if (lane == 31) warp_sums[wid] = x;
    __syncthreads();
    if (wid == 0) {
        int y = warp_sums[lane];
        #pragma unroll
        for (int d = 1; d < 32; d <<= 1) {
            int z = __shfl_up_sync(0xFFFFFFFFu, y, d);
            if (lane >= d) y += z;
        }
        warp_sums[lane] = y;
    }
    __syncthreads();
    if (i < N_NODES) {
        int excl = x - v + (wid ? warp_sums[wid - 1] : 0) + s_blkoff + i;
        g_off[i] = excl;
        g_csr_src[excl] = i;       // self loop in first slot
        g_cursor[i] = excl + 1;
    }
    if (i == 0) g_off[N_NODES] = E_TOT;
}

// 4 edges per thread: int4 loads of src+dst, 4 independent atomics in flight
__global__ void k_scatter(const int* __restrict__ ei) {
    int e0 = (blockIdx.x * blockDim.x + threadIdx.x) * 4;
    if (e0 + 4 <= N_EDGES) {
        int4 sv = *reinterpret_cast<const int4*>(&ei[e0]);
        int4 dv = *reinterpret_cast<const int4*>(&ei[N_EDGES + e0]);
        int p0 = atomicAdd(&g_cursor[dv.x], 1);
        int p1 = atomicAdd(&g_cursor[dv.y], 1);
        int p2 = atomicAdd(&g_cursor[dv.z], 1);
        int p3 = atomicAdd(&g_cursor[dv.w], 1);
        g_csr_src[p0] = sv.x;
        g_csr_src[p1] = sv.y;
        g_csr_src[p2] = sv.z;
        g_csr_src[p3] = sv.w;
    } else {
        for (int e = e0; e < N_EDGES; ++e) {
            int pos = atomicAdd(&g_cursor[ei[N_EDGES + e]], 1);
            g_csr_src[pos] = ei[e];
        }
    }
}

// ---------------- layer 1: node transform, 32 nodes/block -------------------
__global__ void k_node1(const float* __restrict__ x, const int* __restrict__ tids,
                        const float* __restrict__ temb, const float* __restrict__ W1,
                        const float* __restrict__ as1, const float* __restrict__ ad1) {
    __shared__ float sW[21 * 64];
    __shared__ float sxin[4][21];
    int t = threadIdx.x;
    for (int i = t; i < 21 * 64; i += 256) sW[i] = W1[i];
    int nl = t >> 6, c = t & 63;
    #pragma unroll 1
    for (int it = 0; it < 8; ++it) {
        int node = blockIdx.x * 32 + it * 4 + nl;
        __syncthreads();
        if (node < N_NODES && c < 21)
            sxin[nl][c] = (c < 5) ? x[node * 5 + c] : temb[tids[node] * 16 + (c - 5)];
        __syncthreads();
        if (node >= N_NODES) continue;
        float h = 0.f;
        #pragma unroll
        for (int k = 0; k < 21; k++) h += sxin[nl][k] * sW[k * 64 + c];
        g_h1[node * 64 + c] = __float2half_rn(h);
        int head = c >> 5;
        float ps = h * as1[c], pd = h * ad1[c];
        #pragma unroll
        for (int d = 16; d; d >>= 1) {
            ps += __shfl_xor_sync(0xFFFFFFFFu, ps, d);
            pd += __shfl_xor_sync(0xFFFFFFFFu, pd, d);
        }
        if ((c & 31) == 0) {
            g_al1[node * 4 + head]     = ps;
            g_al1[node * 4 + 2 + head] = pd;
        }
    }
}

// ---------------- layer 1 aggregation: warp/dst, shuffle-batched, MLP=8 -----
// Lane l owns channels [2l, 2l+1]; lanes 0-15 = head0, 16-31 = head1.
__global__ void k_agg1(const float* __restrict__ b1) {
    int w = (blockIdx.x * blockDim.x + threadIdx.x) >> 5;
    int lane = threadIdx.x & 31;
    if (w >= N_NODES) return;
    int dst = w;
    float ald0 = g_al1[dst * 4 + 2], ald1 = g_al1[dst * 4 + 3];
    int beg = g_off[dst], end = g_off[dst + 1];
    float2 acc = make_float2(0.f, 0.f);
    float sw0 = 0.f, sw1 = 0.f;
    for (int base = beg; base < end; base += 32) {
        int K = end - base; K = (K > 32) ? 32 : K;
        int myidx = 0; float w0 = 0.f, w1 = 0.f;
        if (lane < K) {
            myidx = __ldg(&g_csr_src[base + lane]);
            float4 a = *reinterpret_cast<const float4*>(&g_al1[myidx * 4]);
            float e0 = a.x + ald0; e0 = (e0 > 0.f) ? e0 : NEG_SLOPE * e0;
            float e1 = a.y + ald1; e1 = (e1 > 0.f) ? e1 : NEG_SLOPE * e1;
            w0 = __expf(e0); w1 = __expf(e1);
            sw0 += w0; sw1 += w1;
        }
        int j = 0;
        for (; j + 8 <= K; j += 8) {
            int ss[8];
            #pragma unroll
            for (int q = 0; q < 8; q++) ss[q] = __shfl_sync(0xFFFFFFFFu, myidx, j + q);
            __half2 hh[8];
            #pragma unroll
            for (int q = 0; q < 8; q++)
                hh[q] = __ldg(reinterpret_cast<const __half2*>(&g_h1[ss[q] * 64 + 2 * lane]));
            #pragma unroll
            for (int q = 0; q < 8; q++) {
                float wa = __shfl_sync(0xFFFFFFFFu, w0, j + q);
                float wb = __shfl_sync(0xFFFFFFFFu, w1, j + q);
                float ws = (lane < 16) ? wa : wb;
                float2 f = __half22float2(hh[q]);
                acc.x += ws * f.x; acc.y += ws * f.y;
            }
        }
        for (; j + 4 <= K; j += 4) {
            int ss[4];
            #pragma unroll
            for (int q = 0; q < 4; q++) ss[q] = __shfl_sync(0xFFFFFFFFu, myidx, j + q);
            __half2 hh[4];
            #pragma unroll
            for (int q = 0; q < 4; q++)
                hh[q] = __ldg(reinterpret_cast<const __half2*>(&g_h1[ss[q] * 64 + 2 * lane]));
            #pragma unroll
            for (int q = 0; q < 4; q++) {
                float wa = __shfl_sync(0xFFFFFFFFu, w0, j + q);
                float wb = __shfl_sync(0xFFFFFFFFu, w1, j + q);
                float ws = (lane < 16) ? wa : wb;
                float2 f = __half22float2(hh[q]);
                acc.x += ws * f.x; acc.y += ws * f.y;
            }
        }
        for (; j < K; ++j) {
            int s = __shfl_sync(0xFFFFFFFFu, myidx, j);
            float wa = __shfl_sync(0xFFFFFFFFu, w0, j);
            float wb = __shfl_sync(0xFFFFFFFFu, w1, j);
            float ws = (lane < 16) ? wa : wb;
            float2 f = __half22float2(
                __ldg(reinterpret_cast<const __half2*>(&g_h1[s * 64 + 2 * lane])));
            acc.x += ws * f.x; acc.y += ws * f.y;
        }
    }
    #pragma unroll
    for (int d = 16; d; d >>= 1) {
        sw0 += __shfl_xor_sync(0xFFFFFFFFu, sw0, d);
        sw1 += __shfl_xor_sync(0xFFFFFFFFu, sw1, d);
    }
    float inv = 1.f / (((lane < 16) ? sw0 : sw1) + 1e-16f);
    float r0 = acc.x * inv + b1[2 * lane];
    float r1 = acc.y * inv + b1[2 * lane + 1];
    float2 o = make_float2(fmaxf(r0, 0.f), fmaxf(r1, 0.f));
    *reinterpret_cast<float2*>(&g_hin2[dst * 64 + 2 * lane]) = o;
}

// ---------------- layer 2: node transform, 32 nodes/block -------------------
__global__ void k_node2(const float* __restrict__ W2,
                        const float* __restrict__ as2, const float* __restrict__ ad2) {
    __shared__ float sW[64 * 64];
    __shared__ float shin[4][64];
    __shared__ float s_part[4][2][2];
    int t = threadIdx.x;
    for (int i = t; i < 64 * 64; i += 256) sW[i] = W2[i];
    int nl = t >> 6, c = t & 63;
    #pragma unroll 1
    for (int it = 0; it < 8; ++it) {
        int node = blockIdx.x * 32 + it * 4 + nl;
        __syncthreads();
        if (node < N_NODES) shin[nl][c] = g_hin2[node * 64 + c];
        __syncthreads();
        if (node >= N_NODES) continue;
        float h = 0.f;
        #pragma unroll
        for (int k = 0; k < 64; k++) h += shin[nl][k] * sW[k * 64 + c];
        g_h2[node * 64 + c] = __float2half_rn(h);
        float ps = h * as2[c], pd = h * ad2[c];
        #pragma unroll
        for (int d = 16; d; d >>= 1) {
            ps += __shfl_xor_sync(0xFFFFFFFFu, ps, d);
            pd += __shfl_xor_sync(0xFFFFFFFFu, pd, d);
        }
        if ((c & 31) == 0) { s_part[nl][c >> 5][0] = ps; s_part[nl][c >> 5][1] = pd; }
        __syncthreads();
        if (c == 0) {
            g_al2[node * 2 + 0] = s_part[nl][0][0] + s_part[nl][1][0];
            g_al2[node * 2 + 1] = s_part[nl][0][1] + s_part[nl][1][1];
        }
    }
}

// ---------------- layer 2 aggregation + bias + LayerNorm, MLP=8 -------------
__global__ void k_agg2(const float* __restrict__ b2, const float* __restrict__ gamma,
                       const float* __restrict__ beta, float* __restrict__ out) {
    int w = (blockIdx.x * blockDim.x + threadIdx.x) >> 5;
    int lane = threadIdx.x & 31;
    if (w >= N_NODES) return;
    int dst = w;
    float ald = g_al2[dst * 2 + 1];
    int beg = g_off[dst], end = g_off[dst + 1];
    float2 acc = make_float2(0.f, 0.f);
    float sw = 0.f;
    for (int base = beg; base < end; base += 32) {
        int K = end - base; K = (K > 32) ? 32 : K;
        int myidx = 0; float w0 = 0.f;
        if (lane < K) {
            myidx = __ldg(&g_csr_src[base + lane]);
            float a = __ldg(&g_al2[myidx * 2]);
            float e = a + ald; e = (e > 0.f) ? e : NEG_SLOPE * e;
            w0 = __expf(e);
            sw += w0;
        }
        int j = 0;
        for (; j + 8 <= K; j += 8) {
            int ss[8];
            #pragma unroll
            for (int q = 0; q < 8; q++) ss[q] = __shfl_sync(0xFFFFFFFFu, myidx, j + q);
            __half2 hh[8];
            #pragma unroll
            for (int q = 0; q < 8; q++)
                hh[q] = __ldg(reinterpret_cast<const __half2*>(&g_h2[ss[q] * 64 + 2 * lane]));
            #pragma unroll
            for (int q = 0; q < 8; q++) {
                float ws = __shfl_sync(0xFFFFFFFFu, w0, j + q);
                float2 f = __half22float2(hh[q]);
                acc.x += ws * f.x; acc.y += ws * f.y;
            }
        }
        for (; j + 4 <= K; j += 4) {
            int ss[4];
            #pragma unroll
            for (int q = 0; q < 4; q++) ss[q] = __shfl_sync(0xFFFFFFFFu, myidx, j + q);
            __half2 hh[4];
            #pragma unroll
            for (int q = 0; q < 4; q++)
                hh[q] = __ldg(reinterpret_cast<const __half2*>(&g_h2[ss[q] * 64 + 2 * lane]));
            #pragma unroll
            for (int q = 0; q < 4; q++) {
                float ws = __shfl_sync(0xFFFFFFFFu, w0, j + q);
                float2 f = __half22float2(hh[q]);
                acc.x += ws * f.x; acc.y += ws * f.y;
            }
        }
        for (; j < K; ++j) {
            int s = __shfl_sync(0xFFFFFFFFu, myidx, j);
            float ws = __shfl_sync(0xFFFFFFFFu, w0, j);
            float2 f = __half22float2(
                __ldg(reinterpret_cast<const __half2*>(&g_h2[s * 64 + 2 * lane])));
            acc.x += ws * f.x; acc.y += ws * f.y;
        }
    }
    #pragma unroll
    for (int d = 16; d; d >>= 1) sw += __shfl_xor_sync(0xFFFFFFFFu, sw, d);
    float inv = 1.f / (sw + 1e-16f);
    float r0 = acc.x * inv + b2[2 * lane];
    float r1 = acc.y * inv + b2[2 * lane + 1];
    float sum = r0 + r1;
    #pragma unroll
    for (int d = 16; d; d >>= 1) sum += __shfl_xor_sync(0xFFFFFFFFu, sum, d);
    float mean = sum * (1.f / 64.f);
    float d0 = r0 - mean, d1 = r1 - mean;
    float sq = d0 * d0 + d1 * d1;
    #pragma unroll
    for (int d = 16; d; d >>= 1) sq += __shfl_xor_sync(0xFFFFFFFFu, sq, d);
    float rstd = rsqrtf(sq * (1.f / 64.f) + 1e-5f);
    float2 o;
    o.x = d0 * rstd * gamma[2 * lane]     + beta[2 * lane];
    o.y = d1 * rstd * gamma[2 * lane + 1] + beta[2 * lane + 1];
    *reinterpret_cast<float2*>(&out[dst * 64 + 2 * lane]) = o;
}

// ---------------- launch ----------------------------------------------------
extern "C" void kernel_launch(void* const* d_in, const int* in_sizes, int n_in,
                              void* d_out, int out_size) {
    const float *x = nullptr, *temb = nullptr, *W1 = nullptr, *W2 = nullptr;
    const int *ei = nullptr, *tids = nullptr;
    const float* v64[8] = {nullptr};
    int n64 = 0;
    for (int i = 0; i < n_in; i++) {
        switch (in_sizes[i]) {
            case 500000:  x    = (const float*)d_in[i]; break;
            case 6400000: ei   = (const int*)d_in[i];   break;
            case 100000:  tids = (const int*)d_in[i];   break;
            case 128:     temb = (const float*)d_in[i]; break;
            case 1344:    W1   = (const float*)d_in[i]; break;
            case 4096:    W2   = (const float*)d_in[i]; break;
            case 64:      if (n64 < 8) v64[n64++] = (const float*)d_in[i]; break;
            default: break;
        }
    }
    const float* as1 = v64[0]; const float* ad1 = v64[1]; const float* b1 = v64[2];
    const float* as2 = v64[3]; const float* ad2 = v64[4]; const float* b2 = v64[5];
    const float* gamma = v64[6]; const float* beta = v64[7];
    float* out = (float*)d_out;

    const int EQ4 = (N_EDGES + 3) / 4;   // edges processed 4-per-thread
    k_init   <<<(N_NODES + 255) / 256, 256>>>();
    k_hist   <<<(EQ4 + 255) / 256, 256>>>(ei);
    k_scan_a <<<N_TILES, 1024>>>();
    k_scan_c <<<N_TILES, 1024>>>();
    k_scatter<<<(EQ4 + 255) / 256, 256>>>(ei);
    k_node1  <<<(N_NODES + 31) / 32, 256>>>(x, tids, temb, W1, as1, ad1);
    k_agg1   <<<(N_NODES + 7) / 8, 256>>>(b1);
    k_node2  <<<(N_NODES + 31) / 32, 256>>>(W2, as2, ad2);
    k_agg2   <<<(N_NODES + 7) / 8, 256>>>(b2, gamma, beta, out);
}

// round 13
// speedup vs baseline: 1.0923x; 1.0923x over previous
#include <cuda_runtime.h>
#include <cuda_fp16.h>
#include <cuda_bf16.h>

#define N_NODES 100000
#define N_EDGES 3200000
#define E_TOT   (N_EDGES + N_NODES)
#define NEG_SLOPE 0.2f
#define N_TILES 98   // ceil(100000 / 1024)

// ---------------- device scratch (allocation-free contract) ----------------
__device__ int g_cnt[N_NODES];
__device__ int g_off[N_NODES + 1];
__device__ int g_cursor[N_NODES];
__device__ int g_csr_src[E_TOT];
__device__ int g_blk[N_TILES];

__device__ __align__(16) __half g_h1[N_NODES * 64];  // layer-1 features (half gather table)
__device__ __align__(8)  float g_als1[N_NODES * 2];  // src-side logits, dense gather table
__device__ __align__(8)  float g_ald1[N_NODES * 2];  // dst-side logits, per-dst read
__device__ __align__(16) float g_hin2[N_NODES * 64]; // relu(layer-1 out), fp32 for matmul
__device__ __align__(16) __half g_h2[N_NODES * 64];  // layer-2 features (half gather table)
__device__ float g_als2[N_NODES];                    // src-side logit, dense gather table
__device__ float g_ald2[N_NODES];                    // dst-side logit

// ---------------- CSR build ----------------
__global__ void k_init() {
    int i = blockIdx.x * blockDim.x + threadIdx.x;
    if (i < N_NODES) g_cnt[i] = 0;
}

__global__ void k_hist(const int* __restrict__ ei) {
    int e = blockIdx.x * blockDim.x + threadIdx.x;
    if (e < N_EDGES) atomicAdd(&g_cnt[ei[N_EDGES + e]], 1);   // dst row
}

// phase A: per-tile (1024) sums
__global__ void k_scan_a() {
    __shared__ int ws[32];
    int tid = threadIdx.x, lane = tid & 31, wid = tid >> 5;
    int i = blockIdx.x * 1024 + tid;
    int v = (i < N_NODES) ? g_cnt[i] : 0;
    #pragma unroll
    for (int d = 16; d; d >>= 1) v += __shfl_xor_sync(0xFFFFFFFFu, v, d);
    if (lane == 0) ws[wid] = v;
    __syncthreads();
    if (wid == 0) {
        int y = ws[lane];
        #pragma unroll
        for (int d = 16; d; d >>= 1) y += __shfl_xor_sync(0xFFFFFFFFu, y, d);
        if (lane == 0) g_blk[blockIdx.x] = y;
    }
}

// phase C: per-tile rescan + inline tile-offset + self-loop emission
// off[i] = exclusive_scan(cnt)[i] + i ; self-loop in slot off[i], edges after.
__global__ void k_scan_c() {
    __shared__ int warp_sums[32];
    __shared__ int s_blkoff;
    int tid = threadIdx.x, lane = tid & 31, wid = tid >> 5;
    if (wid == 0) {
        int ssum = 0;
        for (int j = lane; j < blockIdx.x; j += 32) ssum += g_blk[j];
        #pragma unroll
        for (int d = 16; d; d >>= 1) ssum += __shfl_xor_sync(0xFFFFFFFFu, ssum, d);
        if (lane == 0) s_blkoff = ssum;
    }
    int i = blockIdx.x * 1024 + tid;
    int v = (i < N_NODES) ? g_cnt[i] : 0;
    int x = v;
    #pragma unroll
    for (int d = 1; d < 32; d <<= 1) {
        int y = __shfl_up_sync(0xFFFFFFFFu, x, d);
        if (lane >= d) x += y;
    }
    if (lane == 31) warp_sums[wid] = x;
    __syncthreads();
    if (wid == 0) {
        int y = warp_sums[lane];
        #pragma unroll
        for (int d = 1; d < 32; d <<= 1) {
            int z = __shfl_up_sync(0xFFFFFFFFu, y, d);
            if (lane >= d) y += z;
        }
        warp_sums[lane] = y;
    }
    __syncthreads();
    if (i < N_NODES) {
        int excl = x - v + (wid ? warp_sums[wid - 1] : 0) + s_blkoff + i;
        g_off[i] = excl;
        g_csr_src[excl] = i;       // self loop in first slot
        g_cursor[i] = excl + 1;
    }
    if (i == 0) g_off[N_NODES] = E_TOT;
}

__global__ void k_scatter(const int* __restrict__ ei) {
    int e = blockIdx.x * blockDim.x + threadIdx.x;
    if (e >= N_EDGES) return;
    int src = ei[e], dst = ei[N_EDGES + e];
    int pos = atomicAdd(&g_cursor[dst], 1);
    g_csr_src[pos] = src;
}

// ---------------- layer 1: node transform, 32 nodes/block -------------------
__global__ void k_node1(const float* __restrict__ x, const int* __restrict__ tids,
                        const float* __restrict__ temb, const float* __restrict__ W1,
                        const float* __restrict__ as1, const float* __restrict__ ad1) {
    __shared__ float sW[21 * 64];
    __shared__ float sxin[4][21];
    int t = threadIdx.x;
    for (int i = t; i < 21 * 64; i += 256) sW[i] = W1[i];
    int nl = t >> 6, c = t & 63;
    #pragma unroll 1
    for (int it = 0; it < 8; ++it) {
        int node = blockIdx.x * 32 + it * 4 + nl;
        __syncthreads();
        if (node < N_NODES && c < 21)
            sxin[nl][c] = (c < 5) ? x[node * 5 + c] : temb[tids[node] * 16 + (c - 5)];
        __syncthreads();
        if (node >= N_NODES) continue;
        float h = 0.f;
        #pragma unroll
        for (int k = 0; k < 21; k++) h += sxin[nl][k] * sW[k * 64 + c];
        g_h1[node * 64 + c] = __float2half_rn(h);
        int head = c >> 5;
        float ps = h * as1[c], pd = h * ad1[c];
        #pragma unroll
        for (int d = 16; d; d >>= 1) {
            ps += __shfl_xor_sync(0xFFFFFFFFu, ps, d);
            pd += __shfl_xor_sync(0xFFFFFFFFu, pd, d);
        }
        if ((c & 31) == 0) {
            g_als1[node * 2 + head] = ps;
            g_ald1[node * 2 + head] = pd;
        }
    }
}

// ---------------- layer 1 aggregation: warp/dst, shuffle-batched (R10) ------
// Lane l owns channels [2l, 2l+1]; lanes 0-15 = head0, 16-31 = head1.
__global__ void k_agg1(const float* __restrict__ b1) {
    int w = (blockIdx.x * blockDim.x + threadIdx.x) >> 5;
    int lane = threadIdx.x & 31;
    if (w >= N_NODES) return;
    int dst = w;
    float2 aldv = *reinterpret_cast<const float2*>(&g_ald1[dst * 2]);
    float ald0 = aldv.x, ald1 = aldv.y;
    int beg = g_off[dst], end = g_off[dst + 1];
    float2 acc = make_float2(0.f, 0.f);
    float sw0 = 0.f, sw1 = 0.f;
    for (int base = beg; base < end; base += 32) {
        int K = end - base; K = (K > 32) ? 32 : K;
        int myidx = 0; float w0 = 0.f, w1 = 0.f;
        if (lane < K) {
            myidx = __ldg(&g_csr_src[base + lane]);
            float2 a = __ldg(reinterpret_cast<const float2*>(&g_als1[myidx * 2]));
            float e0 = a.x + ald0; e0 = (e0 > 0.f) ? e0 : NEG_SLOPE * e0;
            float e1 = a.y + ald1; e1 = (e1 > 0.f) ? e1 : NEG_SLOPE * e1;
            w0 = __expf(e0); w1 = __expf(e1);
            sw0 += w0; sw1 += w1;
        }
        int j = 0;
        for (; j + 4 <= K; j += 4) {
            int s0 = __shfl_sync(0xFFFFFFFFu, myidx, j);
            int s1 = __shfl_sync(0xFFFFFFFFu, myidx, j + 1);
            int s2 = __shfl_sync(0xFFFFFFFFu, myidx, j + 2);
            int s3 = __shfl_sync(0xFFFFFFFFu, myidx, j + 3);
            __half2 h0 = __ldg(reinterpret_cast<const __half2*>(&g_h1[s0 * 64 + 2 * lane]));
            __half2 h1 = __ldg(reinterpret_cast<const __half2*>(&g_h1[s1 * 64 + 2 * lane]));
            __half2 h2 = __ldg(reinterpret_cast<const __half2*>(&g_h1[s2 * 64 + 2 * lane]));
            __half2 h3 = __ldg(reinterpret_cast<const __half2*>(&g_h1[s3 * 64 + 2 * lane]));
            float2 f0 = __half22float2(h0);
            float2 f1 = __half22float2(h1);
            float2 f2 = __half22float2(h2);
            float2 f3 = __half22float2(h3);
            float wa, wb, ws;
            wa = __shfl_sync(0xFFFFFFFFu, w0, j);     wb = __shfl_sync(0xFFFFFFFFu, w1, j);
            ws = (lane < 16) ? wa : wb; acc.x += ws * f0.x; acc.y += ws * f0.y;
            wa = __shfl_sync(0xFFFFFFFFu, w0, j + 1); wb = __shfl_sync(0xFFFFFFFFu, w1, j + 1);
            ws = (lane < 16) ? wa : wb; acc.x += ws * f1.x; acc.y += ws * f1.y;
            wa = __shfl_sync(0xFFFFFFFFu, w0, j + 2); wb = __shfl_sync(0xFFFFFFFFu, w1, j + 2);
            ws = (lane < 16) ? wa : wb; acc.x += ws * f2.x; acc.y += ws * f2.y;
            wa = __shfl_sync(0xFFFFFFFFu, w0, j + 3); wb = __shfl_sync(0xFFFFFFFFu, w1, j + 3);
            ws = (lane < 16) ? wa : wb; acc.x += ws * f3.x; acc.y += ws * f3.y;
        }
        for (; j < K; ++j) {
            int s = __shfl_sync(0xFFFFFFFFu, myidx, j);
            float wa = __shfl_sync(0xFFFFFFFFu, w0, j);
            float wb = __shfl_sync(0xFFFFFFFFu, w1, j);
            float ws = (lane < 16) ? wa : wb;
            float2 f = __half22float2(
                __ldg(reinterpret_cast<const __half2*>(&g_h1[s * 64 + 2 * lane])));
            acc.x += ws * f.x; acc.y += ws * f.y;
        }
    }
    #pragma unroll
    for (int d = 16; d; d >>= 1) {
        sw0 += __shfl_xor_sync(0xFFFFFFFFu, sw0, d);
        sw1 += __shfl_xor_sync(0xFFFFFFFFu, sw1, d);
    }
    float inv = 1.f / (((lane < 16) ? sw0 : sw1) + 1e-16f);
    float r0 = acc.x * inv + b1[2 * lane];
    float r1 = acc.y * inv + b1[2 * lane + 1];
    float2 o = make_float2(fmaxf(r0, 0.f), fmaxf(r1, 0.f));
    *reinterpret_cast<float2*>(&g_hin2[dst * 64 + 2 * lane]) = o;
}

// ---------------- layer 2: node transform, 32 nodes/block -------------------
__global__ void k_node2(const float* __restrict__ W2,
                        const float* __restrict__ as2, const float* __restrict__ ad2) {
    __shared__ float sW[64 * 64];
    __shared__ float shin[4][64];
    __shared__ float s_part[4][2][2];
    int t = threadIdx.x;
    for (int i = t; i < 64 * 64; i += 256) sW[i] = W2[i];
    int nl = t >> 6, c = t & 63;
    #pragma unroll 1
    for (int it = 0; it < 8; ++it) {
        int node = blockIdx.x * 32 + it * 4 + nl;
        __syncthreads();
        if (node < N_NODES) shin[nl][c] = g_hin2[node * 64 + c];
        __syncthreads();
        if (node >= N_NODES) continue;
        float h = 0.f;
        #pragma unroll
        for (int k = 0; k < 64; k++) h += shin[nl][k] * sW[k * 64 + c];
        g_h2[node * 64 + c] = __float2half_rn(h);
        float ps = h * as2[c], pd = h * ad2[c];
        #pragma unroll
        for (int d = 16; d; d >>= 1) {
            ps += __shfl_xor_sync(0xFFFFFFFFu, ps, d);
            pd += __shfl_xor_sync(0xFFFFFFFFu, pd, d);
        }
        if ((c & 31) == 0) { s_part[nl][c >> 5][0] = ps; s_part[nl][c >> 5][1] = pd; }
        __syncthreads();
        if (c == 0) {
            g_als2[node] = s_part[nl][0][0] + s_part[nl][1][0];
            g_ald2[node] = s_part[nl][0][1] + s_part[nl][1][1];
        }
    }
}

// ---------------- layer 2 aggregation + bias + LayerNorm (R10) --------------
__global__ void k_agg2(const float* __restrict__ b2, const float* __restrict__ gamma,
                       const float* __restrict__ beta, float* __restrict__ out) {
    int w = (blockIdx.x * blockDim.x + threadIdx.x) >> 5;
    int lane = threadIdx.x & 31;
    if (w >= N_NODES) return;
    int dst = w;
    float ald = g_ald2[dst];
    int beg = g_off[dst], end = g_off[dst + 1];
    float2 acc = make_float2(0.f, 0.f);
    float sw = 0.f;
    for (int base = beg; base < end; base += 32) {
        int K = end - base; K = (K > 32) ? 32 : K;
        int myidx = 0; float w0 = 0.f;
        if (lane < K) {
            myidx = __ldg(&g_csr_src[base + lane]);
            float a = __ldg(&g_als2[myidx]);
            float e = a + ald; e = (e > 0.f) ? e : NEG_SLOPE * e;
            w0 = __expf(e);
            sw += w0;
        }
        int j = 0;
        for (; j + 4 <= K; j += 4) {
            int s0 = __shfl_sync(0xFFFFFFFFu, myidx, j);
            int s1 = __shfl_sync(0xFFFFFFFFu, myidx, j + 1);
            int s2 = __shfl_sync(0xFFFFFFFFu, myidx, j + 2);
            int s3 = __shfl_sync(0xFFFFFFFFu, myidx, j + 3);
            __half2 h0 = __ldg(reinterpret_cast<const __half2*>(&g_h2[s0 * 64 + 2 * lane]));
            __half2 h1 = __ldg(reinterpret_cast<const __half2*>(&g_h2[s1 * 64 + 2 * lane]));
            __half2 h2 = __ldg(reinterpret_cast<const __half2*>(&g_h2[s2 * 64 + 2 * lane]));
            __half2 h3 = __ldg(reinterpret_cast<const __half2*>(&g_h2[s3 * 64 + 2 * lane]));
            float2 f0 = __half22float2(h0);
            float2 f1 = __half22float2(h1);
            float2 f2 = __half22float2(h2);
            float2 f3 = __half22float2(h3);
            float ws;
            ws = __shfl_sync(0xFFFFFFFFu, w0, j);     acc.x += ws * f0.x; acc.y += ws * f0.y;
            ws = __shfl_sync(0xFFFFFFFFu, w0, j + 1); acc.x += ws * f1.x; acc.y += ws * f1.y;
            ws = __shfl_sync(0xFFFFFFFFu, w0, j + 2); acc.x += ws * f2.x; acc.y += ws * f2.y;
            ws = __shfl_sync(0xFFFFFFFFu, w0, j + 3); acc.x += ws * f3.x; acc.y += ws * f3.y;
        }
        for (; j < K; ++j) {
            int s = __shfl_sync(0xFFFFFFFFu, myidx, j);
            float ws = __shfl_sync(0xFFFFFFFFu, w0, j);
            float2 f = __half22float2(
                __ldg(reinterpret_cast<const __half2*>(&g_h2[s * 64 + 2 * lane])));
            acc.x += ws * f.x; acc.y += ws * f.y;
        }
    }
    #pragma unroll
    for (int d = 16; d; d >>= 1) sw += __shfl_xor_sync(0xFFFFFFFFu, sw, d);
    float inv = 1.f / (sw + 1e-16f);
    float r0 = acc.x * inv + b2[2 * lane];
    float r1 = acc.y * inv + b2[2 * lane + 1];
    float sum = r0 + r1;
    #pragma unroll
    for (int d = 16; d; d >>= 1) sum += __shfl_xor_sync(0xFFFFFFFFu, sum, d);
    float mean = sum * (1.f / 64.f);
    float d0 = r0 - mean, d1 = r1 - mean;
    float sq = d0 * d0 + d1 * d1;
    #pragma unroll
    for (int d = 16; d; d >>= 1) sq += __shfl_xor_sync(0xFFFFFFFFu, sq, d);
    float rstd = rsqrtf(sq * (1.f / 64.f) + 1e-5f);
    float2 o;
    o.x = d0 * rstd * gamma[2 * lane]     + beta[2 * lane];
    o.y = d1 * rstd * gamma[2 * lane + 1] + beta[2 * lane + 1];
    *reinterpret_cast<float2*>(&out[dst * 64 + 2 * lane]) = o;
}

// ---------------- launch ----------------------------------------------------
extern "C" void kernel_launch(void* const* d_in, const int* in_sizes, int n_in,
                              void* d_out, int out_size) {
    const float *x = nullptr, *temb = nullptr, *W1 = nullptr, *W2 = nullptr;
    const int *ei = nullptr, *tids = nullptr;
    const float* v64[8] = {nullptr};
    int n64 = 0;
    for (int i = 0; i < n_in; i++) {
        switch (in_sizes[i]) {
            case 500000:  x    = (const float*)d_in[i]; break;
            case 6400000: ei   = (const int*)d_in[i];   break;
            case 100000:  tids = (const int*)d_in[i];   break;
            case 128:     temb = (const float*)d_in[i]; break;
            case 1344:    W1   = (const float*)d_in[i]; break;
            case 4096:    W2   = (const float*)d_in[i]; break;
            case 64:      if (n64 < 8) v64[n64++] = (const float*)d_in[i]; break;
            default: break;
        }
    }
    const float* as1 = v64[0]; const float* ad1 = v64[1]; const float* b1 = v64[2];
    const float* as2 = v64[3]; const float* ad2 = v64[4]; const float* b2 = v64[5];
    const float* gamma = v64[6]; const float* beta = v64[7];
    float* out = (float*)d_out;

    k_init   <<<(N_NODES + 255) / 256, 256>>>();
    k_hist   <<<(N_EDGES + 255) / 256, 256>>>(ei);
    k_scan_a <<<N_TILES, 1024>>>();
    k_scan_c <<<N_TILES, 1024>>>();
    k_scatter<<<(N_EDGES + 255) / 256, 256>>>(ei);
    k_node1  <<<(N_NODES + 31) / 32, 256>>>(x, tids, temb, W1, as1, ad1);
    k_agg1   <<<(N_NODES + 7) / 8, 256>>>(b1);
    k_node2  <<<(N_NODES + 31) / 32, 256>>>(W2, as2, ad2);
    k_agg2   <<<(N_NODES + 7) / 8, 256>>>(b2, gamma, beta, out);
}

// round 16
// speedup vs baseline: 1.1066x; 1.0131x over previous
#include <cuda_runtime.h>
#include <cuda_fp16.h>
#include <cuda_bf16.h>

#define N_NODES 100000
#define N_EDGES 3200000
#define E_TOT   (N_EDGES + N_NODES)
#define NEG_SLOPE 0.2f
#define N_TILES 98   // ceil(100000 / 1024)

// ---------------- device scratch (allocation-free contract) ----------------
__device__ int g_cnt[N_NODES];
__device__ int g_off[N_NODES + 1];
__device__ int g_cursor[N_NODES];
__device__ int g_csr_src[E_TOT];
__device__ int g_blk[N_TILES];

__device__ __align__(16) __half g_h1[N_NODES * 64];  // layer-1 features (half gather table)
__device__ __align__(16) float g_al1[N_NODES * 4];   // [als0, als1, ald0, ald1]
__device__ __align__(16) float g_hin2[N_NODES * 64]; // relu(layer-1 out), fp32 for matmul
__device__ __align__(16) __half g_h2[N_NODES * 64];  // layer-2 features (half gather table)
__device__ __align__(8)  float g_al2[N_NODES * 2];   // [als, ald]

// ---------------- CSR build ----------------
__global__ void k_init() {
    int i = blockIdx.x * blockDim.x + threadIdx.x;
    if (i < N_NODES) g_cnt[i] = 0;
}

// 4 edges per thread, int4 load, 4 independent atomics in flight
__global__ void k_hist(const int* __restrict__ ei) {
    int e0 = (blockIdx.x * blockDim.x + threadIdx.x) * 4;
    if (e0 + 4 <= N_EDGES) {
        int4 d = *reinterpret_cast<const int4*>(&ei[N_EDGES + e0]);
        atomicAdd(&g_cnt[d.x], 1);
        atomicAdd(&g_cnt[d.y], 1);
        atomicAdd(&g_cnt[d.z], 1);
        atomicAdd(&g_cnt[d.w], 1);
    } else {
        for (int e = e0; e < N_EDGES; ++e) atomicAdd(&g_cnt[ei[N_EDGES + e]], 1);
    }
}

// phase A: per-tile (1024) sums
__global__ void k_scan_a() {
    __shared__ int ws[32];
    int tid = threadIdx.x, lane = tid & 31, wid = tid >> 5;
    int i = blockIdx.x * 1024 + tid;
    int v = (i < N_NODES) ? g_cnt[i] : 0;
    #pragma unroll
    for (int d = 16; d; d >>= 1) v += __shfl_xor_sync(0xFFFFFFFFu, v, d);
    if (lane == 0) ws[wid] = v;
    __syncthreads();
    if (wid == 0) {
        int y = ws[lane];
        #pragma unroll
        for (int d = 16; d; d >>= 1) y += __shfl_xor_sync(0xFFFFFFFFu, y, d);
        if (lane == 0) g_blk[blockIdx.x] = y;
    }
}

// phase C: per-tile rescan + inline tile-offset + self-loop emission
// off[i] = exclusive_scan(cnt)[i] + i ; self-loop in slot off[i], edges after.
__global__ void k_scan_c() {
    __shared__ int warp_sums[32];
    __shared__ int s_blkoff;
    int tid = threadIdx.x, lane = tid & 31, wid = tid >> 5;
    if (wid == 0) {
        int ssum = 0;
        for (int j = lane; j < blockIdx.x; j += 32) ssum += g_blk[j];
        #pragma unroll
        for (int d = 16; d; d >>= 1) ssum += __shfl_xor_sync(0xFFFFFFFFu, ssum, d);
        if (lane == 0) s_blkoff = ssum;
    }
    int i = blockIdx.x * 1024 + tid;
    int v = (i < N_NODES) ? g_cnt[i] : 0;
    int x = v;
    #pragma unroll
    for (int d = 1; d < 32; d <<= 1) {
        int y = __shfl_up_sync(0xFFFFFFFFu, x, d);
        if (lane >= d) x += y;
    }
    if (lane == 31) warp_sums[wid] = x;
    __syncthreads();
    if (wid == 0) {
        int y = warp_sums[lane];
        #pragma unroll
        for (int d = 1; d < 32; d <<= 1) {
            int z = __shfl_up_sync(0xFFFFFFFFu, y, d);
            if (lane >= d) y += z;
        }
        warp_sums[lane] = y;
    }
    __syncthreads();
    if (i < N_NODES) {
        int excl = x - v + (wid ? warp_sums[wid - 1] : 0) + s_blkoff + i;
        g_off[i] = excl;
        g_csr_src[excl] = i;       // self loop in first slot
        g_cursor[i] = excl + 1;
    }
    if (i == 0) g_off[N_NODES] = E_TOT;
}

// 4 edges per thread: int4 loads, 4 independent atomic+store chains in flight
__global__ void k_scatter(const int* __restrict__ ei) {
    int e0 = (blockIdx.x * blockDim.x + threadIdx.x) * 4;
    if (e0 + 4 <= N_EDGES) {
        int4 sv = *reinterpret_cast<const int4*>(&ei[e0]);
        int4 dv = *reinterpret_cast<const int4*>(&ei[N_EDGES + e0]);
        int p0 = atomicAdd(&g_cursor[dv.x], 1);
        int p1 = atomicAdd(&g_cursor[dv.y], 1);
        int p2 = atomicAdd(&g_cursor[dv.z], 1);
        int p3 = atomicAdd(&g_cursor[dv.w], 1);
        g_csr_src[p0] = sv.x;
        g_csr_src[p1] = sv.y;
        g_csr_src[p2] = sv.z;
        g_csr_src[p3] = sv.w;
    } else {
        for (int e = e0; e < N_EDGES; ++e) {
            int pos = atomicAdd(&g_cursor[ei[N_EDGES + e]], 1);
            g_csr_src[pos] = ei[e];
        }
    }
}

// ---------------- layer 1: node transform, 32 nodes/block -------------------
__global__ void k_node1(const float* __restrict__ x, const int* __restrict__ tids,
                        const float* __restrict__ temb, const float* __restrict__ W1,
                        const float* __restrict__ as1, const float* __restrict__ ad1) {
    __shared__ float sW[21 * 64];
    __shared__ float sxin[4][21];
    int t = threadIdx.x;
    for (int i = t; i < 21 * 64; i += 256) sW[i] = W1[i];
    int nl = t >> 6, c = t & 63;
    #pragma unroll 1
    for (int it = 0; it < 8; ++it) {
        int node = blockIdx.x * 32 + it * 4 + nl;
        __syncthreads();
        if (node < N_NODES && c < 21)
            sxin[nl][c] = (c < 5) ? x[node * 5 + c] : temb[tids[node] * 16 + (c - 5)];
        __syncthreads();
        if (node >= N_NODES) continue;
        float h = 0.f;
        #pragma unroll
        for (int k = 0; k < 21; k++) h += sxin[nl][k] * sW[k * 64 + c];
        g_h1[node * 64 + c] = __float2half_rn(h);
        int head = c >> 5;
        float ps = h * as1[c], pd = h * ad1[c];
        #pragma unroll
        for (int d = 16; d; d >>= 1) {
            ps += __shfl_xor_sync(0xFFFFFFFFu, ps, d);
            pd += __shfl_xor_sync(0xFFFFFFFFu, pd, d);
        }
        if ((c & 31) == 0) {
            g_al1[node * 4 + head]     = ps;
            g_al1[node * 4 + 2 + head] = pd;
        }
    }
}

// ---------------- layer 1 aggregation: warp/dst, shuffle-batched (R10) ------
// Lane l owns channels [2l, 2l+1]; lanes 0-15 = head0, 16-31 = head1.
__global__ void k_agg1(const float* __restrict__ b1) {
    int w = (blockIdx.x * blockDim.x + threadIdx.x) >> 5;
    int lane = threadIdx.x & 31;
    if (w >= N_NODES) return;
    int dst = w;
    float ald0 = g_al1[dst * 4 + 2], ald1 = g_al1[dst * 4 + 3];
    int beg = g_off[dst], end = g_off[dst + 1];
    float2 acc = make_float2(0.f, 0.f);
    float sw0 = 0.f, sw1 = 0.f;
    for (int base = beg; base < end; base += 32) {
        int K = end - base; K = (K > 32) ? 32 : K;
        int myidx = 0; float w0 = 0.f, w1 = 0.f;
        if (lane < K) {
            myidx = __ldg(&g_csr_src[base + lane]);
            float4 a = *reinterpret_cast<const float4*>(&g_al1[myidx * 4]);
            float e0 = a.x + ald0; e0 = (e0 > 0.f) ? e0 : NEG_SLOPE * e0;
            float e1 = a.y + ald1; e1 = (e1 > 0.f) ? e1 : NEG_SLOPE * e1;
            w0 = __expf(e0); w1 = __expf(e1);
            sw0 += w0; sw1 += w1;
        }
        int j = 0;
        for (; j + 4 <= K; j += 4) {
            int s0 = __shfl_sync(0xFFFFFFFFu, myidx, j);
            int s1 = __shfl_sync(0xFFFFFFFFu, myidx, j + 1);
            int s2 = __shfl_sync(0xFFFFFFFFu, myidx, j + 2);
            int s3 = __shfl_sync(0xFFFFFFFFu, myidx, j + 3);
            __half2 h0 = __ldg(reinterpret_cast<const __half2*>(&g_h1[s0 * 64 + 2 * lane]));
            __half2 h1 = __ldg(reinterpret_cast<const __half2*>(&g_h1[s1 * 64 + 2 * lane]));
            __half2 h2 = __ldg(reinterpret_cast<const __half2*>(&g_h1[s2 * 64 + 2 * lane]));
            __half2 h3 = __ldg(reinterpret_cast<const __half2*>(&g_h1[s3 * 64 + 2 * lane]));
            float2 f0 = __half22float2(h0);
            float2 f1 = __half22float2(h1);
            float2 f2 = __half22float2(h2);
            float2 f3 = __half22float2(h3);
            float wa, wb, ws;
            wa = __shfl_sync(0xFFFFFFFFu, w0, j);     wb = __shfl_sync(0xFFFFFFFFu, w1, j);
            ws = (lane < 16) ? wa : wb; acc.x += ws * f0.x; acc.y += ws * f0.y;
            wa = __shfl_sync(0xFFFFFFFFu, w0, j + 1); wb = __shfl_sync(0xFFFFFFFFu, w1, j + 1);
            ws = (lane < 16) ? wa : wb; acc.x += ws * f1.x; acc.y += ws * f1.y;
            wa = __shfl_sync(0xFFFFFFFFu, w0, j + 2); wb = __shfl_sync(0xFFFFFFFFu, w1, j + 2);
            ws = (lane < 16) ? wa : wb; acc.x += ws * f2.x; acc.y += ws * f2.y;
            wa = __shfl_sync(0xFFFFFFFFu, w0, j + 3); wb = __shfl_sync(0xFFFFFFFFu, w1, j + 3);
            ws = (lane < 16) ? wa : wb; acc.x += ws * f3.x; acc.y += ws * f3.y;
        }
        for (; j < K; ++j) {
            int s = __shfl_sync(0xFFFFFFFFu, myidx, j);
            float wa = __shfl_sync(0xFFFFFFFFu, w0, j);
            float wb = __shfl_sync(0xFFFFFFFFu, w1, j);
            float ws = (lane < 16) ? wa : wb;
            float2 f = __half22float2(
                __ldg(reinterpret_cast<const __half2*>(&g_h1[s * 64 + 2 * lane])));
            acc.x += ws * f.x; acc.y += ws * f.y;
        }
    }
    #pragma unroll
    for (int d = 16; d; d >>= 1) {
        sw0 += __shfl_xor_sync(0xFFFFFFFFu, sw0, d);
        sw1 += __shfl_xor_sync(0xFFFFFFFFu, sw1, d);
    }
    float inv = 1.f / (((lane < 16) ? sw0 : sw1) + 1e-16f);
    float r0 = acc.x * inv + b1[2 * lane];
    float r1 = acc.y * inv + b1[2 * lane + 1];
    float2 o = make_float2(fmaxf(r0, 0.f), fmaxf(r1, 0.f));
    *reinterpret_cast<float2*>(&g_hin2[dst * 64 + 2 * lane]) = o;
}

// ---------------- layer 2: node transform, 32 nodes/block -------------------
__global__ void k_node2(const float* __restrict__ W2,
                        const float* __restrict__ as2, const float* __restrict__ ad2) {
    __shared__ float sW[64 * 64];
    __shared__ float shin[4][64];
    __shared__ float s_part[4][2][2];
    int t = threadIdx.x;
    for (int i = t; i < 64 * 64; i += 256) sW[i] = W2[i];
    int nl = t >> 6, c = t & 63;
    #pragma unroll 1
    for (int it = 0; it < 8; ++it) {
        int node = blockIdx.x * 32 + it * 4 + nl;
        __syncthreads();
        if (node < N_NODES) shin[nl][c] = g_hin2[node * 64 + c];
        __syncthreads();
        if (node >= N_NODES) continue;
        float h = 0.f;
        #pragma unroll
        for (int k = 0; k < 64; k++) h += shin[nl][k] * sW[k * 64 + c];
        g_h2[node * 64 + c] = __float2half_rn(h);
        float ps = h * as2[c], pd = h * ad2[c];
        #pragma unroll
        for (int d = 16; d; d >>= 1) {
            ps += __shfl_xor_sync(0xFFFFFFFFu, ps, d);
            pd += __shfl_xor_sync(0xFFFFFFFFu, pd, d);
        }
        if ((c & 31) == 0) { s_part[nl][c >> 5][0] = ps; s_part[nl][c >> 5][1] = pd; }
        __syncthreads();
        if (c == 0) {
            g_al2[node * 2 + 0] = s_part[nl][0][0] + s_part[nl][1][0];
            g_al2[node * 2 + 1] = s_part[nl][0][1] + s_part[nl][1][1];
        }
    }
}

// ---------------- layer 2 aggregation + bias + LayerNorm (R10) --------------
__global__ void k_agg2(const float* __restrict__ b2, const float* __restrict__ gamma,
                       const float* __restrict__ beta, float* __restrict__ out) {
    int w = (blockIdx.x * blockDim.x + threadIdx.x) >> 5;
    int lane = threadIdx.x & 31;
    if (w >= N_NODES) return;
    int dst = w;
    float ald = g_al2[dst * 2 + 1];
    int beg = g_off[dst], end = g_off[dst + 1];
    float2 acc = make_float2(0.f, 0.f);
    float sw = 0.f;
    for (int base = beg; base < end; base += 32) {
        int K = end - base; K = (K > 32) ? 32 : K;
        int myidx = 0; float w0 = 0.f;
        if (lane < K) {
            myidx = __ldg(&g_csr_src[base + lane]);
            float a = __ldg(&g_al2[myidx * 2]);
            float e = a + ald; e = (e > 0.f) ? e : NEG_SLOPE * e;
            w0 = __expf(e);
            sw += w0;
        }
        int j = 0;
        for (; j + 4 <= K; j += 4) {
            int s0 = __shfl_sync(0xFFFFFFFFu, myidx, j);
            int s1 = __shfl_sync(0xFFFFFFFFu, myidx, j + 1);
            int s2 = __shfl_sync(0xFFFFFFFFu, myidx, j + 2);
            int s3 = __shfl_sync(0xFFFFFFFFu, myidx, j + 3);
            __half2 h0 = __ldg(reinterpret_cast<const __half2*>(&g_h2[s0 * 64 + 2 * lane]));
            __half2 h1 = __ldg(reinterpret_cast<const __half2*>(&g_h2[s1 * 64 + 2 * lane]));
            __half2 h2 = __ldg(reinterpret_cast<const __half2*>(&g_h2[s2 * 64 + 2 * lane]));
            __half2 h3 = __ldg(reinterpret_cast<const __half2*>(&g_h2[s3 * 64 + 2 * lane]));
            float2 f0 = __half22float2(h0);
            float2 f1 = __half22float2(h1);
            float2 f2 = __half22float2(h2);
            float2 f3 = __half22float2(h3);
            float ws;
            ws = __shfl_sync(0xFFFFFFFFu, w0, j);     acc.x += ws * f0.x; acc.y += ws * f0.y;
            ws = __shfl_sync(0xFFFFFFFFu, w0, j + 1); acc.x += ws * f1.x; acc.y += ws * f1.y;
            ws = __shfl_sync(0xFFFFFFFFu, w0, j + 2); acc.x += ws * f2.x; acc.y += ws * f2.y;
            ws = __shfl_sync(0xFFFFFFFFu, w0, j + 3); acc.x += ws * f3.x; acc.y += ws * f3.y;
        }
        for (; j < K; ++j) {
            int s = __shfl_sync(0xFFFFFFFFu, myidx, j);
            float ws = __shfl_sync(0xFFFFFFFFu, w0, j);
            float2 f = __half22float2(
                __ldg(reinterpret_cast<const __half2*>(&g_h2[s * 64 + 2 * lane])));
            acc.x += ws * f.x; acc.y += ws * f.y;
        }
    }
    #pragma unroll
    for (int d = 16; d; d >>= 1) sw += __shfl_xor_sync(0xFFFFFFFFu, sw, d);
    float inv = 1.f / (sw + 1e-16f);
    float r0 = acc.x * inv + b2[2 * lane];
    float r1 = acc.y * inv + b2[2 * lane + 1];
    float sum = r0 + r1;
    #pragma unroll
    for (int d = 16; d; d >>= 1) sum += __shfl_xor_sync(0xFFFFFFFFu, sum, d);
    float mean = sum * (1.f / 64.f);
    float d0 = r0 - mean, d1 = r1 - mean;
    float sq = d0 * d0 + d1 * d1;
    #pragma unroll
    for (int d = 16; d; d >>= 1) sq += __shfl_xor_sync(0xFFFFFFFFu, sq, d);
    float rstd = rsqrtf(sq * (1.f / 64.f) + 1e-5f);
    float2 o;
    o.x = d0 * rstd * gamma[2 * lane]     + beta[2 * lane];
    o.y = d1 * rstd * gamma[2 * lane + 1] + beta[2 * lane + 1];
    *reinterpret_cast<float2*>(&out[dst * 64 + 2 * lane]) = o;
}

// ---------------- launch ----------------------------------------------------
extern "C" void kernel_launch(void* const* d_in, const int* in_sizes, int n_in,
                              void* d_out, int out_size) {
    const float *x = nullptr, *temb = nullptr, *W1 = nullptr, *W2 = nullptr;
    const int *ei = nullptr, *tids = nullptr;
    const float* v64[8] = {nullptr};
    int n64 = 0;
    for (int i = 0; i < n_in; i++) {
        switch (in_sizes[i]) {
            case 500000:  x    = (const float*)d_in[i]; break;
            case 6400000: ei   = (const int*)d_in[i];   break;
            case 100000:  tids = (const int*)d_in[i];   break;
            case 128:     temb = (const float*)d_in[i]; break;
            case 1344:    W1   = (const float*)d_in[i]; break;
            case 4096:    W2   = (const float*)d_in[i]; break;
            case 64:      if (n64 < 8) v64[n64++] = (const float*)d_in[i]; break;
            default: break;
        }
    }
    const float* as1 = v64[0]; const float* ad1 = v64[1]; const float* b1 = v64[2];
    const float* as2 = v64[3]; const float* ad2 = v64[4]; const float* b2 = v64[5];
    const float* gamma = v64[6]; const float* beta = v64[7];
    float* out = (float*)d_out;

    const int EQ4 = (N_EDGES + 3) / 4;   // edges processed 4-per-thread
    k_init   <<<(N_NODES + 255) / 256, 256>>>();
    k_hist   <<<(EQ4 + 255) / 256, 256>>>(ei);
    k_scan_a <<<N_TILES, 1024>>>();
    k_scan_c <<<N_TILES, 1024>>>();
    k_scatter<<<(EQ4 + 255) / 256, 256>>>(ei);
    k_node1  <<<(N_NODES + 31) / 32, 256>>>(x, tids, temb, W1, as1, ad1);
    k_agg1   <<<(N_NODES + 7) / 8, 256>>>(b1);
    k_node2  <<<(N_NODES + 31) / 32, 256>>>(W2, as2, ad2);
    k_agg2   <<<(N_NODES + 7) / 8, 256>>>(b2, gamma, beta, out);
}